// round 5
// baseline (speedup 1.0000x reference)
#include <cuda_runtime.h>

// VisibilityHeatmap: per (b,k) keypoint, NDC coord -> pixel index, gather ONE
// heatmap value, threshold, broadcast mask to both coord lanes.
//
// coords [B=32,K=64,2] f32, heatmaps [B,K,256,256] f32, out [B,K,2] f32.
// Latency-bound micro-kernel: 2048 independent gathers, ~260KB touched.
//
// Launch-shape history (harness wall time):
//   R2: 8 CTAs x 256 thr, 1 kp/thread   -> 4.64 us  (best)
//   R3: 4 CTAs x 256 thr, 2 kp/thread   -> 6.91 us  (too few SMs + divergence)
//   R4: 64 CTAs x 32 thr, 1 kp/thread   -> 6.85 us  (grid-walk overhead)
// => 8x256 is the optimum: 8 SMs x 8 warps, full latency hiding, minimal
//    dispatch overhead. This round = R2 exactly, minus the bounds guard
//    (2048 = 8*256 exact fit).

#define THRESHOLD 0.4f

__global__ void __launch_bounds__(256, 1)
vis_heatmap_kernel(const float* __restrict__ coords,
                   const float* __restrict__ heatmaps,
                   float* __restrict__ out)
{
    int i = blockIdx.x * 256 + threadIdx.x;   // exact fit, no guard

    // Coalesced vectorized coord load: (u, v) NDC
    float2 c = reinterpret_cast<const float2*>(coords)[i];

    // ndc -> pixel, truncate toward zero (matches .astype(int32))
    int u = (int)((c.x + 1.0f) * 128.0f);   // 0.5 * WIDTH  = 128
    int v = (int)((c.y + 1.0f) * 128.0f);   // 0.5 * HEIGHT = 128

    // valid iff 0 <= u < 256 and 0 <= v < 256
    bool valid = ((unsigned)u < 256u) & ((unsigned)v < 256u);

    // Predicated gather: invalid lanes output 0 regardless, so skip the load.
    float val = 0.0f;
    if (valid) {
        // heatmaps[i][v][u] = base + ((i<<16) | (v<<8) | u)
        unsigned idx = ((unsigned)i << 16) | ((unsigned)v << 8) | (unsigned)u;
        val = __ldg(&heatmaps[idx]);
    }

    float m = (val > THRESHOLD) ? 1.0f : 0.0f;

    // Coalesced vectorized store: broadcast mask to both lanes
    reinterpret_cast<float2*>(out)[i] = make_float2(m, m);
}

extern "C" void kernel_launch(void* const* d_in, const int* in_sizes, int n_in,
                              void* d_out, int out_size)
{
    const float* coords   = (const float*)d_in[0];
    const float* heatmaps = (const float*)d_in[1];
    float* out = (float*)d_out;

    int n = in_sizes[0] / 2;           // B*K = 2048 keypoints
    int blocks = (n + 255) / 256;      // = 8
    vis_heatmap_kernel<<<blocks, 256>>>(coords, heatmaps, out);
}

// round 6
// speedup vs baseline: 1.0435x; 1.0435x over previous
#include <cuda_runtime.h>

// VisibilityHeatmap: per (b,k) keypoint, NDC coord -> pixel index, gather ONE
// heatmap value, threshold, broadcast mask to both coord lanes.
//
// coords [B=32,K=64,2] f32, heatmaps [B,K,256,256] f32, out [B,K,2] f32.
// Latency-bound micro-kernel: 2048 independent gathers, ~260KB touched
// (L2-resident under graph replay). Measured floor ~4.6us; R2..R5 showed the
// harness timing is clock-state bimodal (~4.6 vs ~6.9us for identical code).
//
// Shape: 8 CTAs x 256 threads, 1 keypoint/thread (empirical best).
// This round: fully branchless body (no BSSY/BSYNC), FMA ndc->pixel,
// clamped always-load + masked threshold (matches reference semantics:
// reference also clamps indices and masks the result).

#define THRESHOLD 0.4f

__global__ void __launch_bounds__(256, 1)
vis_heatmap_kernel(const float* __restrict__ coords,
                   const float* __restrict__ heatmaps,
                   float* __restrict__ out)
{
    int i = blockIdx.x * 256 + threadIdx.x;   // exact fit (2048 = 8*256)

    // Coalesced vectorized coord load: (u, v) NDC
    float2 c = reinterpret_cast<const float2*>(coords)[i];

    // ndc -> pixel via single FMA each; truncate toward zero (.astype(int32))
    int u = (int)__fmaf_rn(c.x, 128.0f, 128.0f);   // (x+1)*0.5*256
    int v = (int)__fmaf_rn(c.y, 128.0f, 128.0f);

    // valid iff 0 <= u < 256 and 0 <= v < 256 (one unsigned compare each)
    bool valid = ((unsigned)u < 256u) & ((unsigned)v < 256u);

    // Clamp to bounds and ALWAYS load (branchless; reference also clamps
    // then masks). Clamped (u,v) in [0,256) -> bitfield address.
    int uc = min(max(u, 0), 255);
    int vc = min(max(v, 0), 255);
    unsigned idx = ((unsigned)i << 16) | ((unsigned)vc << 8) | (unsigned)uc;
    float val = __ldg(&heatmaps[idx]);

    float m = (valid & (val > THRESHOLD)) ? 1.0f : 0.0f;

    // Coalesced vectorized store: broadcast mask to both lanes
    reinterpret_cast<float2*>(out)[i] = make_float2(m, m);
}

extern "C" void kernel_launch(void* const* d_in, const int* in_sizes, int n_in,
                              void* d_out, int out_size)
{
    const float* coords   = (const float*)d_in[0];
    const float* heatmaps = (const float*)d_in[1];
    float* out = (float*)d_out;

    int n = in_sizes[0] / 2;           // B*K = 2048 keypoints
    int blocks = (n + 255) / 256;      // = 8
    vis_heatmap_kernel<<<blocks, 256>>>(coords, heatmaps, out);
}